// round 12
// baseline (speedup 1.0000x reference)
#include <cuda_runtime.h>
#include <cuda_bf16.h>
#include <cstdint>

#define NH   16
#define DH   64
#define HID  1024
#define NB   4
#define SL   2048
#define MROWS (NB*SL)                 // 8192
#define QKVN ((size_t)NB*NH*SL*DH)    // 8.4M

// ---------------------------------------------------------------------------
// Global scratch (allocation-free): pre-split bf16 hi/lo operands
// ---------------------------------------------------------------------------
__device__ __nv_bfloat16 g_xh[(size_t)MROWS*HID], g_xl[(size_t)MROWS*HID];
__device__ __nv_bfloat16 g_Wh[4][(size_t)HID*HID], g_Wl[4][(size_t)HID*HID];
__device__ __nv_bfloat16 g_Qh[QKVN], g_Ql[QKVN];
__device__ __nv_bfloat16 g_Kh[QKVN], g_Kl[QKVN];
__device__ __nv_bfloat16 g_Vh[QKVN], g_Vl[QKVN];
__device__ __nv_bfloat16 g_Ah[(size_t)MROWS*HID], g_Al[(size_t)MROWS*HID];
__device__ int g_kidx[NB][SL];
__device__ int g_kn[NB];

// ---------------------------------------------------------------------------
// helpers
// ---------------------------------------------------------------------------
__device__ __forceinline__ uint32_t smem_u32(const void* p) {
    return (uint32_t)__cvta_generic_to_shared(p);
}
__device__ __forceinline__ void ldm4(uint32_t r[4], uint32_t a) {
    asm volatile("ldmatrix.sync.aligned.m8n8.x4.shared.b16 {%0,%1,%2,%3},[%4];"
        : "=r"(r[0]), "=r"(r[1]), "=r"(r[2]), "=r"(r[3]) : "r"(a));
}
__device__ __forceinline__ void ldm4t(uint32_t r[4], uint32_t a) {
    asm volatile("ldmatrix.sync.aligned.m8n8.x4.trans.shared.b16 {%0,%1,%2,%3},[%4];"
        : "=r"(r[0]), "=r"(r[1]), "=r"(r[2]), "=r"(r[3]) : "r"(a));
}
__device__ __forceinline__ void mma_bf(float c[4], const uint32_t a[4], const uint32_t b[2]) {
    asm volatile("mma.sync.aligned.m16n8k16.row.col.f32.bf16.bf16.f32 "
                 "{%0,%1,%2,%3},{%4,%5,%6,%7},{%8,%9},{%0,%1,%2,%3};"
        : "+f"(c[0]), "+f"(c[1]), "+f"(c[2]), "+f"(c[3])
        : "r"(a[0]), "r"(a[1]), "r"(a[2]), "r"(a[3]), "r"(b[0]), "r"(b[1]));
}
__device__ __forceinline__ void cp16(uint32_t dst, const void* src) {
    asm volatile("cp.async.cg.shared.global [%0], [%1], 16;" :: "r"(dst), "l"(src));
}
#define CP_COMMIT asm volatile("cp.async.commit_group;" ::: "memory")
#define CP_WAIT2  asm volatile("cp.async.wait_group 2;" ::: "memory")
#define CP_WAIT1  asm volatile("cp.async.wait_group 1;" ::: "memory")
#define CP_WAIT0  asm volatile("cp.async.wait_group 0;" ::: "memory")

__device__ __forceinline__ uint32_t pk(float a, float b) {
    __nv_bfloat162 t = __floats2bfloat162_rn(a, b);
    return *reinterpret_cast<uint32_t*>(&t);
}
__device__ __forceinline__ float bfhi(float x) {
    return __bfloat162float(__float2bfloat16_rn(x));
}
__device__ __forceinline__ void split4(const float4 v, uint32_t hi[2], uint32_t lo[2]) {
    float h0 = bfhi(v.x), h1 = bfhi(v.y), h2 = bfhi(v.z), h3 = bfhi(v.w);
    hi[0] = pk(h0, h1); hi[1] = pk(h2, h3);
    lo[0] = pk(v.x - h0, v.y - h1); lo[1] = pk(v.z - h2, v.w - h3);
}

// ---------------------------------------------------------------------------
// Prep: split fp32 -> bf16 hi/lo (once per element)
// ---------------------------------------------------------------------------
__global__ void split_x_kernel(const float* __restrict__ src)
{
    const size_t n4 = (size_t)MROWS * HID / 4;
    for (size_t i = (size_t)blockIdx.x * blockDim.x + threadIdx.x; i < n4;
         i += (size_t)gridDim.x * blockDim.x) {
        float4 v = ((const float4*)src)[i];
        uint32_t hi[2], lo[2];
        split4(v, hi, lo);
        ((uint2*)g_xh)[i] = make_uint2(hi[0], hi[1]);
        ((uint2*)g_xl)[i] = make_uint2(lo[0], lo[1]);
    }
}

__global__ void split_w_kernel(const float* __restrict__ Wq, const float* __restrict__ Wk,
                               const float* __restrict__ Wv, const float* __restrict__ Wo)
{
    const int z = blockIdx.y;
    const float* src = (z == 0) ? Wq : (z == 1) ? Wk : (z == 2) ? Wv : Wo;
    const size_t n4 = (size_t)HID * HID / 4;
    for (size_t i = (size_t)blockIdx.x * blockDim.x + threadIdx.x; i < n4;
         i += (size_t)gridDim.x * blockDim.x) {
        float4 v = ((const float4*)src)[i];
        uint32_t hi[2], lo[2];
        split4(v, hi, lo);
        ((uint2*)g_Wh[z])[i] = make_uint2(hi[0], hi[1]);
        ((uint2*)g_Wl[z])[i] = make_uint2(lo[0], lo[1]);
    }
}

// ---------------------------------------------------------------------------
// Mask compaction: per batch, indices of unmasked keys + count.
// ---------------------------------------------------------------------------
__global__ void mask_compact_kernel(const int* __restrict__ mask)
{
    const int b = blockIdx.x, t = threadIdx.x;   // 256 threads
    __shared__ int wsum[8];
    int m[8], loc = 0;
    #pragma unroll
    for (int i = 0; i < 8; i++) { m[i] = (mask[b*SL + t*8 + i] != 0); loc += m[i]; }
    int v = loc;
    #pragma unroll
    for (int d = 1; d < 32; d <<= 1) {
        int u = __shfl_up_sync(0xffffffffu, v, d);
        if ((t & 31) >= d) v += u;
    }
    if ((t & 31) == 31) wsum[t >> 5] = v;
    __syncthreads();
    if (t < 8) {
        int s = wsum[t];
        #pragma unroll
        for (int d = 1; d < 8; d <<= 1) {
            int u = __shfl_up_sync(0x000000ffu, s, d);
            if (t >= d) s += u;
        }
        wsum[t] = s;
    }
    __syncthreads();
    int off = v - loc + ((t >= 32) ? wsum[(t >> 5) - 1] : 0);
    #pragma unroll
    for (int i = 0; i < 8; i++)
        if (m[i]) g_kidx[b][off++] = t*8 + i;
    if (t == 0) g_kn[b] = wsum[7];
}

// ---------------------------------------------------------------------------
// bf16x3 GEMM: 4-stage k16 cp.async pipeline, ONE __syncthreads per chunk,
// prefetch issued before compute. CTA 128x128, 8 warps (warp tile 64x32).
// Row pitch 48B: 48*i mod 128 covers 8 distinct 16B banks per ldmatrix phase.
// ---------------------------------------------------------------------------
#define GS_PITCH 48
#define GS_ARR   (128*GS_PITCH)     // 6144 B per array
#define GS_STAGE (4*GS_ARR)         // 24576 B: Ah,Al,Bh,Bl
#define GEMM_SMEM (4*GS_STAGE)      // 98304 B -> 2 CTAs/SM
#define NCH 64                      // 1024 / 16

template<int MODE>
__device__ __forceinline__ void gemm_ca(
    const __nv_bfloat16* __restrict__ Ah_g, const __nv_bfloat16* __restrict__ Al_g,
    const __nv_bfloat16* __restrict__ Bh_g, const __nv_bfloat16* __restrict__ Bl_g,
    const float* __restrict__ bias,
    float* __restrict__ out, __nv_bfloat16* __restrict__ outh, __nv_bfloat16* __restrict__ outl)
{
    extern __shared__ __align__(16) unsigned char sm[];
    const int t = threadIdx.x, lane = t & 31, wid = t >> 5;
    const int wy = wid >> 2, wx = wid & 3;
    const int m0 = blockIdx.y * 128, n0 = blockIdx.x * 128;
    const uint32_t smb = smem_u32(sm);

    float acc[4][4][4];
    #pragma unroll
    for (int mi = 0; mi < 4; mi++)
        #pragma unroll
        for (int ni = 0; ni < 4; ni++)
            #pragma unroll
            for (int r = 0; r < 4; r++) acc[mi][ni][r] = 0.0f;

    auto prefetch = [&](int stage, int c) {
        const int k0 = c * 16;
        const uint32_t stb = smb + stage * GS_STAGE;
        #pragma unroll
        for (int i = 0; i < 4; i++) {
            const int idx = t + i * 256;          // 0..1023
            const int arr = idx >> 8, rem = idx & 255;
            const int r = rem >> 1, g = rem & 1;
            const __nv_bfloat16* src =
                (arr == 0) ? Ah_g + (size_t)(m0 + r) * HID + k0 + g * 8 :
                (arr == 1) ? Al_g + (size_t)(m0 + r) * HID + k0 + g * 8 :
                (arr == 2) ? Bh_g + (size_t)(n0 + r) * HID + k0 + g * 8 :
                             Bl_g + (size_t)(n0 + r) * HID + k0 + g * 8;
            cp16(stb + arr * GS_ARR + r * GS_PITCH + g * 16, src);
        }
        CP_COMMIT;
    };

    prefetch(0, 0);
    prefetch(1, 1);
    prefetch(2, 2);

    for (int c = 0; c < NCH; c++) {
        if (c < NCH - 2)      { CP_WAIT2; }
        else if (c == NCH - 2){ CP_WAIT1; }
        else                  { CP_WAIT0; }
        __syncthreads();
        if (c + 3 < NCH) prefetch((c + 3) & 3, c + 3);

        const uint32_t stb = smb + (c & 3) * GS_STAGE;
        const uint32_t sAh = stb, sAl = stb + GS_ARR;
        const uint32_t sBh = stb + 2*GS_ARR, sBl = stb + 3*GS_ARR;

        // B fragments for nj pairs: one ldm4 covers 16 rows x 2 k-halves
        uint32_t bh[4][2], bl[4][2];
        #pragma unroll
        for (int np = 0; np < 2; np++) {
            const uint32_t off = (uint32_t)((wx*32 + np*16 + (lane & 7)
                                 + ((lane >> 4) & 1)*8) * GS_PITCH
                                 + ((lane >> 3) & 1) * 16);
            uint32_t r4[4];
            ldm4(r4, sBh + off);
            bh[np*2+0][0] = r4[0]; bh[np*2+0][1] = r4[1];
            bh[np*2+1][0] = r4[2]; bh[np*2+1][1] = r4[3];
            ldm4(r4, sBl + off);
            bl[np*2+0][0] = r4[0]; bl[np*2+0][1] = r4[1];
            bl[np*2+1][0] = r4[2]; bl[np*2+1][1] = r4[3];
        }
        #pragma unroll
        for (int mi = 0; mi < 4; mi++) {
            const uint32_t off = (uint32_t)((wy*64 + mi*16 + (lane & 15)) * GS_PITCH
                                 + (lane >> 4) * 16);
            uint32_t ah[4], al_[4];
            ldm4(ah, sAh + off);
            ldm4(al_, sAl + off);
            #pragma unroll
            for (int ni = 0; ni < 4; ni++) {
                mma_bf(acc[mi][ni], ah, bh[ni]);
                mma_bf(acc[mi][ni], ah, bl[ni]);
                mma_bf(acc[mi][ni], al_, bh[ni]);
            }
        }
    }

    const int gid = lane >> 2, tig = lane & 3;
    #pragma unroll
    for (int mi = 0; mi < 4; mi++) {
        const int r0 = m0 + wy*64 + mi*16 + gid;
        #pragma unroll
        for (int ni = 0; ni < 4; ni++) {
            const int col = n0 + wx*32 + ni*8 + 2*tig;
            const float b0 = bias[col], b1 = bias[col+1];
            const float v0 = acc[mi][ni][0] + b0, v1 = acc[mi][ni][1] + b1;
            const float v2 = acc[mi][ni][2] + b0, v3 = acc[mi][ni][3] + b1;
            if (MODE == 0) {
                const int h_ = col >> 6, d = col & 63;
                {
                    const int b_ = r0 >> 11, s_ = r0 & (SL-1);
                    const size_t off = (((size_t)(b_*NH + h_))*SL + s_)*DH + d;
                    const float h0f = bfhi(v0), h1f = bfhi(v1);
                    *(uint32_t*)&outh[off] = pk(h0f, h1f);
                    *(uint32_t*)&outl[off] = pk(v0 - h0f, v1 - h1f);
                }
                {
                    const int r1 = r0 + 8;
                    const int b_ = r1 >> 11, s_ = r1 & (SL-1);
                    const size_t off = (((size_t)(b_*NH + h_))*SL + s_)*DH + d;
                    const float h0f = bfhi(v2), h1f = bfhi(v3);
                    *(uint32_t*)&outh[off] = pk(h0f, h1f);
                    *(uint32_t*)&outl[off] = pk(v2 - h0f, v3 - h1f);
                }
            } else {
                *(float2*)&out[(size_t)r0*HID + col]     = make_float2(v0, v1);
                *(float2*)&out[(size_t)(r0+8)*HID + col] = make_float2(v2, v3);
            }
        }
    }
}

__global__ __launch_bounds__(256, 2) void qkv_ca(
    const float* __restrict__ bq, const float* __restrict__ bk, const float* __restrict__ bv)
{
    const int z = blockIdx.z;
    const float* bias = (z == 0) ? bq : (z == 1) ? bk : bv;
    __nv_bfloat16 *oh, *ol;
    if (z == 0)      { oh = g_Qh; ol = g_Ql; }
    else if (z == 1) { oh = g_Kh; ol = g_Kl; }
    else             { oh = g_Vh; ol = g_Vl; }
    gemm_ca<0>(g_xh, g_xl, g_Wh[z], g_Wl[z], bias, nullptr, oh, ol);
}

__global__ __launch_bounds__(256, 2) void oproj_ca(
    const float* __restrict__ bo, float* __restrict__ out)
{
    gemm_ca<1>(g_Ah, g_Al, g_Wh[3], g_Wl[3], bo, out, nullptr, nullptr);
}

// ---------------------------------------------------------------------------
// Attention with key compaction (unchanged from R11 winner).
// ---------------------------------------------------------------------------
#define CPW1  asm volatile("cp.async.wait_group 1;" ::: "memory")
#define AT_QH    0
#define AT_QL    18432                 // 128*144
#define AT_ST    36864
#define AT_ARR   9216                  // 64*144
#define AT_STAGE (4*AT_ARR)            // Kh,Kl,Vh,Vl
#define ATT_SMEM (AT_ST + 2*AT_STAGE)  // 110592

__global__ __launch_bounds__(128, 2) void attn_ca()
{
    extern __shared__ __align__(16) unsigned char sm[];
    const int t = threadIdx.x, lane = t & 31, w = t >> 5;
    const int gid = lane >> 2, tig = lane & 3;
    const int q0 = blockIdx.x * 128, h = blockIdx.y, b = blockIdx.z;
    const size_t base = ((size_t)(b*NH + h)) * SL * DH;
    const uint32_t smb = smem_u32(sm);
    const uint32_t sQh = smb + AT_QH, sQl = smb + AT_QL;

    int n = g_kn[b];
    if (n < 1) n = 1;
    const int n_m1 = n - 1;
    const int ktn = (n + 63) >> 6;

    #pragma unroll
    for (int i = 0; i < 16; i++) {
        const int g = t + i * 128;
        const int arr = g >> 10, rem = g & 1023;
        const int r = rem >> 3, cg = rem & 7;
        const __nv_bfloat16* src = (arr ? g_Ql : g_Qh) + base + (size_t)(q0 + r)*DH + cg*8;
        cp16(smb + arr*18432 + r*144 + cg*16, src);
    }
    CP_COMMIT;

    auto prefetch = [&](int stage, int kt) {
        const int kb = kt * 64;
        const uint32_t stb = smb + AT_ST + stage * AT_STAGE;
        #pragma unroll
        for (int i = 0; i < 16; i++) {
            const int g = t + i * 128;
            const int arr = g >> 9, rem = g & 511;
            const int r = rem >> 3, cg = rem & 7;
            int j = kb + r; if (j > n_m1) j = n_m1;
            const int row = g_kidx[b][j];
            const __nv_bfloat16* barr =
                (arr == 0) ? g_Kh : (arr == 1) ? g_Kl : (arr == 2) ? g_Vh : g_Vl;
            cp16(stb + arr*AT_ARR + r*144 + cg*16, barr + base + (size_t)row*DH + cg*8);
        }
        CP_COMMIT;
    };

    prefetch(0, 0);
    if (ktn > 1) prefetch(1, 1);

    float o[2][8][4];
    #pragma unroll
    for (int mi = 0; mi < 2; mi++)
        #pragma unroll
        for (int nd = 0; nd < 8; nd++)
            #pragma unroll
            for (int r = 0; r < 4; r++) o[mi][nd][r] = 0.0f;
    float den[4] = {0.f, 0.f, 0.f, 0.f};

    for (int kt = 0; kt < ktn; kt++) {
        if (kt < ktn - 2) { CPW1; } else { CP_WAIT0; }
        __syncthreads();
        const int kb = kt * 64;
        const uint32_t stb = smb + AT_ST + (kt & 1) * AT_STAGE;
        const uint32_t sKh = stb, sKl = stb + AT_ARR;
        const uint32_t sVh = stb + 2*AT_ARR, sVl = stb + 3*AT_ARR;

        float cS[2][8][4];
        #pragma unroll
        for (int mi = 0; mi < 2; mi++)
            #pragma unroll
            for (int nj = 0; nj < 8; nj++)
                #pragma unroll
                for (int r = 0; r < 4; r++) cS[mi][nj][r] = 0.0f;

        #pragma unroll
        for (int ks = 0; ks < 4; ks++) {
            uint32_t ah[2][4], al_[2][4];
            #pragma unroll
            for (int mi = 0; mi < 2; mi++) {
                const uint32_t off = (uint32_t)((w*32 + mi*16 + (lane & 15))*144
                                     + ks*32 + (lane >> 4)*16);
                ldm4(ah[mi], sQh + off);
                ldm4(al_[mi], sQl + off);
            }
            #pragma unroll
            for (int np = 0; np < 4; np++) {
                const uint32_t off = (uint32_t)((np*16 + (lane & 7)
                                     + ((lane >> 4) & 1)*8)*144
                                     + ks*32 + ((lane >> 3) & 1)*16);
                uint32_t kh4[4], kl4[4];
                ldm4(kh4, sKh + off);
                ldm4(kl4, sKl + off);
                uint32_t kh0[2] = {kh4[0], kh4[1]}, kh1[2] = {kh4[2], kh4[3]};
                uint32_t kl0[2] = {kl4[0], kl4[1]}, kl1[2] = {kl4[2], kl4[3]};
                #pragma unroll
                for (int mi = 0; mi < 2; mi++) {
                    mma_bf(cS[mi][np*2+0], ah[mi], kh0);
                    mma_bf(cS[mi][np*2+0], ah[mi], kl0);
                    mma_bf(cS[mi][np*2+0], al_[mi], kh0);
                    mma_bf(cS[mi][np*2+1], ah[mi], kh1);
                    mma_bf(cS[mi][np*2+1], ah[mi], kl1);
                    mma_bf(cS[mi][np*2+1], al_[mi], kh1);
                }
            }
        }

        uint32_t aPh[2][4][4], aPl[2][4][4];
        float rs[4] = {0.f, 0.f, 0.f, 0.f};
        #pragma unroll
        for (int mi = 0; mi < 2; mi++) {
            #pragma unroll
            for (int nj = 0; nj < 8; nj++) {
                const int cbase = kb + nj*8 + 2*tig;
                const int mA = (cbase < n), mB = (cbase + 1 < n);
                float p[4];
                #pragma unroll
                for (int r = 0; r < 4; r++) {
                    float s = cS[mi][nj][r] * 0.125f;
                    s = fminf(fmaxf(s, -50.0f), 50.0f);
                    s = ((r & 1) ? mB : mA) ? s : -50.0f;
                    p[r] = __expf(s);
                }
                rs[mi*2+0] += p[0] + p[1];
                rs[mi*2+1] += p[2] + p[3];
                const float h0f = bfhi(p[0]), h1f = bfhi(p[1]);
                const float h2f = bfhi(p[2]), h3f = bfhi(p[3]);
                aPh[mi][nj >> 1][(nj & 1)*2 + 0] = pk(h0f, h1f);
                aPh[mi][nj >> 1][(nj & 1)*2 + 1] = pk(h2f, h3f);
                aPl[mi][nj >> 1][(nj & 1)*2 + 0] = pk(p[0]-h0f, p[1]-h1f);
                aPl[mi][nj >> 1][(nj & 1)*2 + 1] = pk(p[2]-h2f, p[3]-h3f);
            }
        }
        #pragma unroll
        for (int i = 0; i < 4; i++) {
            float r = rs[i];
            r += __shfl_xor_sync(0xffffffffu, r, 1, 4);
            r += __shfl_xor_sync(0xffffffffu, r, 2, 4);
            den[i] += r;
        }

        #pragma unroll
        for (int ks = 0; ks < 4; ks++) {
            #pragma unroll
            for (int ndp = 0; ndp < 4; ndp++) {
                const uint32_t off = (uint32_t)((ks*16 + (lane & 7)
                                     + ((lane >> 3) & 1)*8)*144
                                     + (ndp*2 + ((lane >> 4) & 1))*16);
                uint32_t vh4[4], vl4[4];
                ldm4t(vh4, sVh + off);
                ldm4t(vl4, sVl + off);
                uint32_t vh0[2] = {vh4[0], vh4[1]}, vh1[2] = {vh4[2], vh4[3]};
                uint32_t vl0[2] = {vl4[0], vl4[1]}, vl1[2] = {vl4[2], vl4[3]};
                #pragma unroll
                for (int mi = 0; mi < 2; mi++) {
                    mma_bf(o[mi][ndp*2+0], aPh[mi][ks], vh0);
                    mma_bf(o[mi][ndp*2+0], aPh[mi][ks], vl0);
                    mma_bf(o[mi][ndp*2+0], aPl[mi][ks], vh0);
                    mma_bf(o[mi][ndp*2+1], aPh[mi][ks], vh1);
                    mma_bf(o[mi][ndp*2+1], aPh[mi][ks], vl1);
                    mma_bf(o[mi][ndp*2+1], aPl[mi][ks], vh1);
                }
            }
        }

        __syncthreads();
        if (kt + 2 < ktn) prefetch(kt & 1, kt + 2);
    }

    #pragma unroll
    for (int mi = 0; mi < 2; mi++) {
        const float inv0 = 1.0f / den[mi*2], inv1 = 1.0f / den[mi*2+1];
        const int r0 = q0 + w*32 + mi*16 + gid, r1 = r0 + 8;
        #pragma unroll
        for (int nd = 0; nd < 8; nd++) {
            const int col = h*DH + nd*8 + 2*tig;
            const float v0 = o[mi][nd][0]*inv0, v1 = o[mi][nd][1]*inv0;
            const float v2 = o[mi][nd][2]*inv1, v3 = o[mi][nd][3]*inv1;
            const float h0f = bfhi(v0), h1f = bfhi(v1);
            const size_t off0 = (size_t)(b*SL + r0)*HID + col;
            *(uint32_t*)&g_Ah[off0] = pk(h0f, h1f);
            *(uint32_t*)&g_Al[off0] = pk(v0 - h0f, v1 - h1f);
            const float h2f = bfhi(v2), h3f = bfhi(v3);
            const size_t off1 = (size_t)(b*SL + r1)*HID + col;
            *(uint32_t*)&g_Ah[off1] = pk(h2f, h3f);
            *(uint32_t*)&g_Al[off1] = pk(v2 - h2f, v3 - h3f);
        }
    }
}

// ---------------------------------------------------------------------------
extern "C" void kernel_launch(void* const* d_in, const int* in_sizes, int n_in,
                              void* d_out, int out_size)
{
    const float* x    = (const float*)d_in[0];
    const int*   mask = (const int*)  d_in[1];
    const float* Wq   = (const float*)d_in[2];
    const float* bq   = (const float*)d_in[3];
    const float* Wk   = (const float*)d_in[4];
    const float* bk   = (const float*)d_in[5];
    const float* Wv   = (const float*)d_in[6];
    const float* bv   = (const float*)d_in[7];
    const float* Wo   = (const float*)d_in[8];
    const float* bo   = (const float*)d_in[9];
    float* out = (float*)d_out;

    cudaFuncSetAttribute(qkv_ca,   cudaFuncAttributeMaxDynamicSharedMemorySize, GEMM_SMEM);
    cudaFuncSetAttribute(oproj_ca, cudaFuncAttributeMaxDynamicSharedMemorySize, GEMM_SMEM);
    cudaFuncSetAttribute(attn_ca,  cudaFuncAttributeMaxDynamicSharedMemorySize, ATT_SMEM);

    split_x_kernel<<<2048, 256>>>(x);
    split_w_kernel<<<dim3(512, 4, 1), 256>>>(Wq, Wk, Wv, Wo);
    mask_compact_kernel<<<NB, 256>>>(mask);

    qkv_ca<<<dim3(HID/128, MROWS/128, 3), 256, GEMM_SMEM>>>(bq, bk, bv);

    attn_ca<<<dim3(SL/128, NH, NB), 128, ATT_SMEM>>>();

    oproj_ca<<<dim3(HID/128, MROWS/128, 1), 256, GEMM_SMEM>>>(bo, out);
}

// round 13
// speedup vs baseline: 1.2450x; 1.2450x over previous
#include <cuda_runtime.h>
#include <cuda_bf16.h>
#include <cstdint>

#define NH   16
#define DH   64
#define HID  1024
#define NB   4
#define SL   2048
#define MROWS (NB*SL)                 // 8192
#define QKVN ((size_t)NB*NH*SL*DH)    // 8.4M

// ---------------------------------------------------------------------------
// Global scratch (allocation-free): pre-split bf16 hi/lo operands
// K/V are stored COMPACTED: slot j of batch b = j-th unmasked key.
// ---------------------------------------------------------------------------
__device__ __nv_bfloat16 g_xh[(size_t)MROWS*HID], g_xl[(size_t)MROWS*HID];
__device__ __nv_bfloat16 g_Wh[4][(size_t)HID*HID], g_Wl[4][(size_t)HID*HID];
__device__ __nv_bfloat16 g_Qh[QKVN], g_Ql[QKVN];
__device__ __nv_bfloat16 g_Kh[QKVN], g_Kl[QKVN];
__device__ __nv_bfloat16 g_Vh[QKVN], g_Vl[QKVN];
__device__ __nv_bfloat16 g_Ah[(size_t)MROWS*HID], g_Al[(size_t)MROWS*HID];
__device__ int g_kidx[NB][SL];
__device__ int g_kn[NB];

// ---------------------------------------------------------------------------
// helpers
// ---------------------------------------------------------------------------
__device__ __forceinline__ uint32_t smem_u32(const void* p) {
    return (uint32_t)__cvta_generic_to_shared(p);
}
__device__ __forceinline__ void ldm4(uint32_t r[4], uint32_t a) {
    asm volatile("ldmatrix.sync.aligned.m8n8.x4.shared.b16 {%0,%1,%2,%3},[%4];"
        : "=r"(r[0]), "=r"(r[1]), "=r"(r[2]), "=r"(r[3]) : "r"(a));
}
__device__ __forceinline__ void ldm4t(uint32_t r[4], uint32_t a) {
    asm volatile("ldmatrix.sync.aligned.m8n8.x4.trans.shared.b16 {%0,%1,%2,%3},[%4];"
        : "=r"(r[0]), "=r"(r[1]), "=r"(r[2]), "=r"(r[3]) : "r"(a));
}
__device__ __forceinline__ void mma_bf(float c[4], const uint32_t a[4], const uint32_t b[2]) {
    asm volatile("mma.sync.aligned.m16n8k16.row.col.f32.bf16.bf16.f32 "
                 "{%0,%1,%2,%3},{%4,%5,%6,%7},{%8,%9},{%0,%1,%2,%3};"
        : "+f"(c[0]), "+f"(c[1]), "+f"(c[2]), "+f"(c[3])
        : "r"(a[0]), "r"(a[1]), "r"(a[2]), "r"(a[3]), "r"(b[0]), "r"(b[1]));
}
__device__ __forceinline__ void cp16(uint32_t dst, const void* src) {
    asm volatile("cp.async.cg.shared.global [%0], [%1], 16;" :: "r"(dst), "l"(src));
}
#define CP_COMMIT asm volatile("cp.async.commit_group;" ::: "memory")
#define CP_WAIT1  asm volatile("cp.async.wait_group 1;" ::: "memory")
#define CP_WAIT0  asm volatile("cp.async.wait_group 0;" ::: "memory")

__device__ __forceinline__ uint32_t pk(float a, float b) {
    __nv_bfloat162 t = __floats2bfloat162_rn(a, b);
    return *reinterpret_cast<uint32_t*>(&t);
}
__device__ __forceinline__ float bfhi(float x) {
    return __bfloat162float(__float2bfloat16_rn(x));
}
__device__ __forceinline__ void split4(const float4 v, uint32_t hi[2], uint32_t lo[2]) {
    float h0 = bfhi(v.x), h1 = bfhi(v.y), h2 = bfhi(v.z), h3 = bfhi(v.w);
    hi[0] = pk(h0, h1); hi[1] = pk(h2, h3);
    lo[0] = pk(v.x - h0, v.y - h1); lo[1] = pk(v.z - h2, v.w - h3);
}

// ---------------------------------------------------------------------------
// Prep: split fp32 -> bf16 hi/lo (once per element)
// ---------------------------------------------------------------------------
__global__ void split_x_kernel(const float* __restrict__ src)
{
    const size_t n4 = (size_t)MROWS * HID / 4;
    for (size_t i = (size_t)blockIdx.x * blockDim.x + threadIdx.x; i < n4;
         i += (size_t)gridDim.x * blockDim.x) {
        float4 v = ((const float4*)src)[i];
        uint32_t hi[2], lo[2];
        split4(v, hi, lo);
        ((uint2*)g_xh)[i] = make_uint2(hi[0], hi[1]);
        ((uint2*)g_xl)[i] = make_uint2(lo[0], lo[1]);
    }
}

__global__ void split_w_kernel(const float* __restrict__ Wq, const float* __restrict__ Wk,
                               const float* __restrict__ Wv, const float* __restrict__ Wo)
{
    const int z = blockIdx.y;
    const float* src = (z == 0) ? Wq : (z == 1) ? Wk : (z == 2) ? Wv : Wo;
    const size_t n4 = (size_t)HID * HID / 4;
    for (size_t i = (size_t)blockIdx.x * blockDim.x + threadIdx.x; i < n4;
         i += (size_t)gridDim.x * blockDim.x) {
        float4 v = ((const float4*)src)[i];
        uint32_t hi[2], lo[2];
        split4(v, hi, lo);
        ((uint2*)g_Wh[z])[i] = make_uint2(hi[0], hi[1]);
        ((uint2*)g_Wl[z])[i] = make_uint2(lo[0], lo[1]);
    }
}

// ---------------------------------------------------------------------------
// Mask compaction: per batch, indices of unmasked keys + count.
// ---------------------------------------------------------------------------
__global__ void mask_compact_kernel(const int* __restrict__ mask)
{
    const int b = blockIdx.x, t = threadIdx.x;   // 256 threads
    __shared__ int wsum[8];
    int m[8], loc = 0;
    #pragma unroll
    for (int i = 0; i < 8; i++) { m[i] = (mask[b*SL + t*8 + i] != 0); loc += m[i]; }
    int v = loc;
    #pragma unroll
    for (int d = 1; d < 32; d <<= 1) {
        int u = __shfl_up_sync(0xffffffffu, v, d);
        if ((t & 31) >= d) v += u;
    }
    if ((t & 31) == 31) wsum[t >> 5] = v;
    __syncthreads();
    if (t < 8) {
        int s = wsum[t];
        #pragma unroll
        for (int d = 1; d < 8; d <<= 1) {
            int u = __shfl_up_sync(0x000000ffu, s, d);
            if (t >= d) s += u;
        }
        wsum[t] = s;
    }
    __syncthreads();
    int off = v - loc + ((t >= 32) ? wsum[(t >> 5) - 1] : 0);
    #pragma unroll
    for (int i = 0; i < 8; i++)
        if (m[i]) g_kidx[b][off++] = t*8 + i;
    if (t == 0) g_kn[b] = wsum[7];
}

// ---------------------------------------------------------------------------
// bf16x3 GEMM (R11 proven shape: 2-stage k32, ldm4-paired B fragments).
// MODE 0: Q -> split-head [B,H,S,D].
// MODE 1: flat fp32 out [M][HID] (oproj).
// MODE 2: K/V compacted: A rows gathered via g_kidx; out slot = compact index.
// ---------------------------------------------------------------------------
#define GS_ARR   10240      // 128 rows * 80B
#define GS_STAGE (4*GS_ARR) // Ah,Al,Bh,Bl
#define GEMM_SMEM (2*GS_STAGE)

template<int MODE>
__device__ __forceinline__ void gemm_ca(
    const __nv_bfloat16* __restrict__ Ah_g, const __nv_bfloat16* __restrict__ Al_g,
    const __nv_bfloat16* __restrict__ Bh_g, const __nv_bfloat16* __restrict__ Bl_g,
    const float* __restrict__ bias,
    float* __restrict__ out, __nv_bfloat16* __restrict__ outh, __nv_bfloat16* __restrict__ outl)
{
    extern __shared__ __align__(16) unsigned char sm[];
    const int t = threadIdx.x, lane = t & 31, wid = t >> 5;
    const int wy = wid >> 2, wx = wid & 3;
    const int m0 = blockIdx.y * 128, n0 = blockIdx.x * 128;
    const uint32_t smb = smem_u32(sm);

    // MODE 2: compact geometry + hoisted gathered A-row bases (2 per thread)
    int b_ = 0, j0 = 0, nv = 0;
    size_t arowA[2] = {0, 0};
    if (MODE == 2) {
        b_ = blockIdx.y >> 4;
        j0 = (blockIdx.y & 15) * 128;
        nv = g_kn[b_];
        #pragma unroll
        for (int p = 0; p < 2; p++) {
            const int r = (p * 256 + t) >> 2;      // local row for i&1 == p
            int j = j0 + r; if (j > nv - 1) j = nv - 1;
            arowA[p] = (size_t)b_ * SL + g_kidx[b_][j];
        }
    }

    float acc[4][4][4];
    #pragma unroll
    for (int mi = 0; mi < 4; mi++)
        #pragma unroll
        for (int ni = 0; ni < 4; ni++)
            #pragma unroll
            for (int r = 0; r < 4; r++) acc[mi][ni][r] = 0.0f;

    auto prefetch = [&](int stage, int c) {
        const int k0 = c * 32;
        const uint32_t stb = smb + stage * GS_STAGE;
        #pragma unroll
        for (int i = 0; i < 8; i++) {
            const int g = t + i * 256;
            const int arr = g >> 9, rem = g & 511;   // arr == i>>1
            const int r = rem >> 2, cg = rem & 3;
            const __nv_bfloat16* src;
            if (MODE == 2 && arr < 2) {
                src = ((arr == 0) ? Ah_g : Al_g) + arowA[i & 1] * HID + k0 + cg * 8;
            } else {
                src =
                    (arr == 0) ? Ah_g + (size_t)(m0 + r) * HID + k0 + cg * 8 :
                    (arr == 1) ? Al_g + (size_t)(m0 + r) * HID + k0 + cg * 8 :
                    (arr == 2) ? Bh_g + (size_t)(n0 + r) * HID + k0 + cg * 8 :
                                 Bl_g + (size_t)(n0 + r) * HID + k0 + cg * 8;
            }
            cp16(stb + arr * GS_ARR + r * 80 + cg * 16, src);
        }
        CP_COMMIT;
    };

    prefetch(0, 0);
    prefetch(1, 1);

    for (int c = 0; c < 32; c++) {
        if (c < 30) { CP_WAIT1; } else { CP_WAIT0; }
        __syncthreads();
        const uint32_t stb = smb + (c & 1) * GS_STAGE;
        const uint32_t sAh = stb, sAl = stb + GS_ARR;
        const uint32_t sBh = stb + 2*GS_ARR, sBl = stb + 3*GS_ARR;
        #pragma unroll
        for (int ks = 0; ks < 32; ks += 16) {
            uint32_t bh[4][2], bl[4][2];
            #pragma unroll
            for (int np = 0; np < 2; np++) {
                const uint32_t off = (uint32_t)((wx*32 + np*16 + (lane & 7)
                                     + ((lane >> 4) & 1)*8) * 80
                                     + ks*2 + ((lane >> 3) & 1) * 16);
                uint32_t r4[4];
                ldm4(r4, sBh + off);
                bh[np*2+0][0] = r4[0]; bh[np*2+0][1] = r4[1];
                bh[np*2+1][0] = r4[2]; bh[np*2+1][1] = r4[3];
                ldm4(r4, sBl + off);
                bl[np*2+0][0] = r4[0]; bl[np*2+0][1] = r4[1];
                bl[np*2+1][0] = r4[2]; bl[np*2+1][1] = r4[3];
            }
            #pragma unroll
            for (int mi = 0; mi < 4; mi++) {
                const uint32_t off = (uint32_t)((wy*64 + mi*16 + (lane & 15)) * 80
                                     + ks*2 + (lane >> 4) * 16);
                uint32_t ah[4], al_[4];
                ldm4(ah, sAh + off);
                ldm4(al_, sAl + off);
                #pragma unroll
                for (int ni = 0; ni < 4; ni++) {
                    mma_bf(acc[mi][ni], ah, bh[ni]);
                    mma_bf(acc[mi][ni], ah, bl[ni]);
                    mma_bf(acc[mi][ni], al_, bh[ni]);
                }
            }
        }
        __syncthreads();
        if (c + 2 < 32) prefetch(c & 1, c + 2);
    }

    const int gid = lane >> 2, tig = lane & 3;
    #pragma unroll
    for (int mi = 0; mi < 4; mi++) {
        const int lr0 = wy*64 + mi*16 + gid;
        #pragma unroll
        for (int ni = 0; ni < 4; ni++) {
            const int col = n0 + wx*32 + ni*8 + 2*tig;
            const float b0 = bias[col], b1 = bias[col+1];
            const float v0 = acc[mi][ni][0] + b0, v1 = acc[mi][ni][1] + b1;
            const float v2 = acc[mi][ni][2] + b0, v3 = acc[mi][ni][3] + b1;
            if (MODE == 0) {
                const int h_ = col >> 6, d = col & 63;
                const int r0 = m0 + lr0;
                {
                    const int bb = r0 >> 11, s_ = r0 & (SL-1);
                    const size_t off = (((size_t)(bb*NH + h_))*SL + s_)*DH + d;
                    const float h0f = bfhi(v0), h1f = bfhi(v1);
                    *(uint32_t*)&outh[off] = pk(h0f, h1f);
                    *(uint32_t*)&outl[off] = pk(v0 - h0f, v1 - h1f);
                }
                {
                    const int r1 = r0 + 8;
                    const int bb = r1 >> 11, s_ = r1 & (SL-1);
                    const size_t off = (((size_t)(bb*NH + h_))*SL + s_)*DH + d;
                    const float h0f = bfhi(v2), h1f = bfhi(v3);
                    *(uint32_t*)&outh[off] = pk(h0f, h1f);
                    *(uint32_t*)&outl[off] = pk(v2 - h0f, v3 - h1f);
                }
            } else if (MODE == 2) {
                const int h_ = col >> 6, d = col & 63;
                {
                    const int j = j0 + lr0;
                    const size_t off = (((size_t)(b_*NH + h_))*SL + j)*DH + d;
                    const float h0f = bfhi(v0), h1f = bfhi(v1);
                    *(uint32_t*)&outh[off] = pk(h0f, h1f);
                    *(uint32_t*)&outl[off] = pk(v0 - h0f, v1 - h1f);
                }
                {
                    const int j = j0 + lr0 + 8;
                    const size_t off = (((size_t)(b_*NH + h_))*SL + j)*DH + d;
                    const float h0f = bfhi(v2), h1f = bfhi(v3);
                    *(uint32_t*)&outh[off] = pk(h0f, h1f);
                    *(uint32_t*)&outl[off] = pk(v2 - h0f, v3 - h1f);
                }
            } else {
                const int r0 = m0 + lr0;
                *(float2*)&out[(size_t)r0*HID + col]     = make_float2(v0, v1);
                *(float2*)&out[(size_t)(r0+8)*HID + col] = make_float2(v2, v3);
            }
        }
    }
}

__global__ __launch_bounds__(256, 2) void qkv_ca(
    const float* __restrict__ bq, const float* __restrict__ bk, const float* __restrict__ bv)
{
    const int z = blockIdx.z;
    if (z == 0) {
        gemm_ca<0>(g_xh, g_xl, g_Wh[0], g_Wl[0], bq, nullptr, g_Qh, g_Ql);
        return;
    }
    const int b_ = blockIdx.y >> 4;
    const int j0 = (blockIdx.y & 15) * 128;
    if (j0 >= g_kn[b_]) return;     // tile entirely beyond compacted keys
    if (z == 1) gemm_ca<2>(g_xh, g_xl, g_Wh[1], g_Wl[1], bk, nullptr, g_Kh, g_Kl);
    else        gemm_ca<2>(g_xh, g_xl, g_Wh[2], g_Wl[2], bv, nullptr, g_Vh, g_Vl);
}

__global__ __launch_bounds__(256, 2) void oproj_ca(
    const float* __restrict__ bo, float* __restrict__ out)
{
    gemm_ca<1>(g_Ah, g_Al, g_Wh[3], g_Wl[3], bo, out, nullptr, nullptr);
}

// ---------------------------------------------------------------------------
// Attention over COMPACTED K/V (contiguous rows, no gather).
// 128 threads (4 warps x 32 q-rows), q-tile 128, k-tile 64, 2 CTAs/SM.
// ---------------------------------------------------------------------------
#define AT_QH    0
#define AT_QL    18432                 // 128*144
#define AT_ST    36864
#define AT_ARR   9216                  // 64*144
#define AT_STAGE (4*AT_ARR)            // Kh,Kl,Vh,Vl
#define ATT_SMEM (AT_ST + 2*AT_STAGE)  // 110592

__global__ __launch_bounds__(128, 2) void attn_ca()
{
    extern __shared__ __align__(16) unsigned char sm[];
    const int t = threadIdx.x, lane = t & 31, w = t >> 5;
    const int gid = lane >> 2, tig = lane & 3;
    const int q0 = blockIdx.x * 128, h = blockIdx.y, b = blockIdx.z;
    const size_t base = ((size_t)(b*NH + h)) * SL * DH;
    const uint32_t smb = smem_u32(sm);
    const uint32_t sQh = smb + AT_QH, sQl = smb + AT_QL;

    int n = g_kn[b];
    if (n < 1) n = 1;
    const int n_m1 = n - 1;
    const int ktn = (n + 63) >> 6;

    #pragma unroll
    for (int i = 0; i < 16; i++) {
        const int g = t + i * 128;
        const int arr = g >> 10, rem = g & 1023;
        const int r = rem >> 3, cg = rem & 7;
        const __nv_bfloat16* src = (arr ? g_Ql : g_Qh) + base + (size_t)(q0 + r)*DH + cg*8;
        cp16(smb + arr*18432 + r*144 + cg*16, src);
    }
    CP_COMMIT;

    auto prefetch = [&](int stage, int kt) {
        const int kb = kt * 64;
        const uint32_t stb = smb + AT_ST + stage * AT_STAGE;
        #pragma unroll
        for (int i = 0; i < 16; i++) {
            const int g = t + i * 128;
            const int arr = g >> 9, rem = g & 511;
            const int r = rem >> 3, cg = rem & 7;
            int j = kb + r; if (j > n_m1) j = n_m1;
            const __nv_bfloat16* barr =
                (arr == 0) ? g_Kh : (arr == 1) ? g_Kl : (arr == 2) ? g_Vh : g_Vl;
            cp16(stb + arr*AT_ARR + r*144 + cg*16, barr + base + (size_t)j*DH + cg*8);
        }
        CP_COMMIT;
    };

    prefetch(0, 0);
    if (ktn > 1) prefetch(1, 1);

    float o[2][8][4];
    #pragma unroll
    for (int mi = 0; mi < 2; mi++)
        #pragma unroll
        for (int nd = 0; nd < 8; nd++)
            #pragma unroll
            for (int r = 0; r < 4; r++) o[mi][nd][r] = 0.0f;
    float den[4] = {0.f, 0.f, 0.f, 0.f};

    for (int kt = 0; kt < ktn; kt++) {
        if (kt < ktn - 2) { CP_WAIT1; } else { CP_WAIT0; }
        __syncthreads();
        const int kb = kt * 64;
        const uint32_t stb = smb + AT_ST + (kt & 1) * AT_STAGE;
        const uint32_t sKh = stb, sKl = stb + AT_ARR;
        const uint32_t sVh = stb + 2*AT_ARR, sVl = stb + 3*AT_ARR;

        float cS[2][8][4];
        #pragma unroll
        for (int mi = 0; mi < 2; mi++)
            #pragma unroll
            for (int nj = 0; nj < 8; nj++)
                #pragma unroll
                for (int r = 0; r < 4; r++) cS[mi][nj][r] = 0.0f;

        #pragma unroll
        for (int ks = 0; ks < 4; ks++) {
            uint32_t ah[2][4], al_[2][4];
            #pragma unroll
            for (int mi = 0; mi < 2; mi++) {
                const uint32_t off = (uint32_t)((w*32 + mi*16 + (lane & 15))*144
                                     + ks*32 + (lane >> 4)*16);
                ldm4(ah[mi], sQh + off);
                ldm4(al_[mi], sQl + off);
            }
            #pragma unroll
            for (int np = 0; np < 4; np++) {
                const uint32_t off = (uint32_t)((np*16 + (lane & 7)
                                     + ((lane >> 4) & 1)*8)*144
                                     + ks*32 + ((lane >> 3) & 1)*16);
                uint32_t kh4[4], kl4[4];
                ldm4(kh4, sKh + off);
                ldm4(kl4, sKl + off);
                uint32_t kh0[2] = {kh4[0], kh4[1]}, kh1[2] = {kh4[2], kh4[3]};
                uint32_t kl0[2] = {kl4[0], kl4[1]}, kl1[2] = {kl4[2], kl4[3]};
                #pragma unroll
                for (int mi = 0; mi < 2; mi++) {
                    mma_bf(cS[mi][np*2+0], ah[mi], kh0);
                    mma_bf(cS[mi][np*2+0], ah[mi], kl0);
                    mma_bf(cS[mi][np*2+0], al_[mi], kh0);
                    mma_bf(cS[mi][np*2+1], ah[mi], kh1);
                    mma_bf(cS[mi][np*2+1], ah[mi], kl1);
                    mma_bf(cS[mi][np*2+1], al_[mi], kh1);
                }
            }
        }

        uint32_t aPh[2][4][4], aPl[2][4][4];
        float rs[4] = {0.f, 0.f, 0.f, 0.f};
        #pragma unroll
        for (int mi = 0; mi < 2; mi++) {
            #pragma unroll
            for (int nj = 0; nj < 8; nj++) {
                const int cbase = kb + nj*8 + 2*tig;
                const int mA = (cbase < n), mB = (cbase + 1 < n);
                float p[4];
                #pragma unroll
                for (int r = 0; r < 4; r++) {
                    float s = cS[mi][nj][r] * 0.125f;
                    s = fminf(fmaxf(s, -50.0f), 50.0f);
                    s = ((r & 1) ? mB : mA) ? s : -50.0f;
                    p[r] = __expf(s);
                }
                rs[mi*2+0] += p[0] + p[1];
                rs[mi*2+1] += p[2] + p[3];
                const float h0f = bfhi(p[0]), h1f = bfhi(p[1]);
                const float h2f = bfhi(p[2]), h3f = bfhi(p[3]);
                aPh[mi][nj >> 1][(nj & 1)*2 + 0] = pk(h0f, h1f);
                aPh[mi][nj >> 1][(nj & 1)*2 + 1] = pk(h2f, h3f);
                aPl[mi][nj >> 1][(nj & 1)*2 + 0] = pk(p[0]-h0f, p[1]-h1f);
                aPl[mi][nj >> 1][(nj & 1)*2 + 1] = pk(p[2]-h2f, p[3]-h3f);
            }
        }
        #pragma unroll
        for (int i = 0; i < 4; i++) {
            float r = rs[i];
            r += __shfl_xor_sync(0xffffffffu, r, 1, 4);
            r += __shfl_xor_sync(0xffffffffu, r, 2, 4);
            den[i] += r;
        }

        #pragma unroll
        for (int ks = 0; ks < 4; ks++) {
            #pragma unroll
            for (int ndp = 0; ndp < 4; ndp++) {
                const uint32_t off = (uint32_t)((ks*16 + (lane & 7)
                                     + ((lane >> 3) & 1)*8)*144
                                     + (ndp*2 + ((lane >> 4) & 1))*16);
                uint32_t vh4[4], vl4[4];
                ldm4t(vh4, sVh + off);
                ldm4t(vl4, sVl + off);
                uint32_t vh0[2] = {vh4[0], vh4[1]}, vh1[2] = {vh4[2], vh4[3]};
                uint32_t vl0[2] = {vl4[0], vl4[1]}, vl1[2] = {vl4[2], vl4[3]};
                #pragma unroll
                for (int mi = 0; mi < 2; mi++) {
                    mma_bf(o[mi][ndp*2+0], aPh[mi][ks], vh0);
                    mma_bf(o[mi][ndp*2+0], aPh[mi][ks], vl0);
                    mma_bf(o[mi][ndp*2+0], aPl[mi][ks], vh0);
                    mma_bf(o[mi][ndp*2+1], aPh[mi][ks], vh1);
                    mma_bf(o[mi][ndp*2+1], aPh[mi][ks], vl1);
                    mma_bf(o[mi][ndp*2+1], aPl[mi][ks], vh1);
                }
            }
        }

        __syncthreads();
        if (kt + 2 < ktn) prefetch(kt & 1, kt + 2);
    }

    #pragma unroll
    for (int mi = 0; mi < 2; mi++) {
        const float inv0 = 1.0f / den[mi*2], inv1 = 1.0f / den[mi*2+1];
        const int r0 = q0 + w*32 + mi*16 + gid, r1 = r0 + 8;
        #pragma unroll
        for (int nd = 0; nd < 8; nd++) {
            const int col = h*DH + nd*8 + 2*tig;
            const float v0 = o[mi][nd][0]*inv0, v1 = o[mi][nd][1]*inv0;
            const float v2 = o[mi][nd][2]*inv1, v3 = o[mi][nd][3]*inv1;
            const float h0f = bfhi(v0), h1f = bfhi(v1);
            const size_t off0 = (size_t)(b*SL + r0)*HID + col;
            *(uint32_t*)&g_Ah[off0] = pk(h0f, h1f);
            *(uint32_t*)&g_Al[off0] = pk(v0 - h0f, v1 - h1f);
            const float h2f = bfhi(v2), h3f = bfhi(v3);
            const size_t off1 = (size_t)(b*SL + r1)*HID + col;
            *(uint32_t*)&g_Ah[off1] = pk(h2f, h3f);
            *(uint32_t*)&g_Al[off1] = pk(v2 - h2f, v3 - h3f);
        }
    }
}

// ---------------------------------------------------------------------------
extern "C" void kernel_launch(void* const* d_in, const int* in_sizes, int n_in,
                              void* d_out, int out_size)
{
    const float* x    = (const float*)d_in[0];
    const int*   mask = (const int*)  d_in[1];
    const float* Wq   = (const float*)d_in[2];
    const float* bq   = (const float*)d_in[3];
    const float* Wk   = (const float*)d_in[4];
    const float* bk   = (const float*)d_in[5];
    const float* Wv   = (const float*)d_in[6];
    const float* bv   = (const float*)d_in[7];
    const float* Wo   = (const float*)d_in[8];
    const float* bo   = (const float*)d_in[9];
    float* out = (float*)d_out;

    cudaFuncSetAttribute(qkv_ca,   cudaFuncAttributeMaxDynamicSharedMemorySize, GEMM_SMEM);
    cudaFuncSetAttribute(oproj_ca, cudaFuncAttributeMaxDynamicSharedMemorySize, GEMM_SMEM);
    cudaFuncSetAttribute(attn_ca,  cudaFuncAttributeMaxDynamicSharedMemorySize, ATT_SMEM);

    split_x_kernel<<<2048, 256>>>(x);
    split_w_kernel<<<dim3(512, 4, 1), 256>>>(Wq, Wk, Wv, Wo);
    mask_compact_kernel<<<NB, 256>>>(mask);

    qkv_ca<<<dim3(HID/128, MROWS/128, 3), 256, GEMM_SMEM>>>(bq, bk, bv);

    attn_ca<<<dim3(SL/128, NH, NB), 128, ATT_SMEM>>>();

    oproj_ca<<<dim3(HID/128, MROWS/128, 1), 256, GEMM_SMEM>>>(bo, out);
}